// round 14
// baseline (speedup 1.0000x reference)
#include <cuda_runtime.h>

#define NROWS 65536   // N_TOKENS * BATCH
#define FDIM  256     // HW
#define MDIM  1024    // MEM_DIM

// ---------------- scratch (static device globals; no allocation) ----------------
__device__ float g_qT[FDIM * NROWS];            // q TRANSPOSED [F, N]            (64 MB)
__device__ float g_qm[NROWS];
__device__ float g_qv[NROWS];
__device__ float g_kcT[FDIM * MDIM];            // centered k, TRANSPOSED [F, M]  (1 MB)
__device__ float g_vmat[MDIM * FDIM];           // v, row-major [M, F]            (1 MB)
__device__ float g_km[MDIM];
__device__ float g_kv[MDIM];
__device__ float g_WqT[FDIM * FDIM];            // Wq transposed [h, j]           (256 KB)
__device__ float g_ST[(size_t)MDIM * NROWS];    // p = exp(ssim) TRANSPOSED [M,N] (256 MB)
__device__ float g_psum[8 * NROWS];             // per-m-block partial col sums   (2 MB)

// ---------------- packed f32x2 helpers (full-rate FP32 on sm_103a) --------------
__device__ __forceinline__ unsigned long long pk2(float lo, float hi) {
    unsigned long long r;
    asm("mov.b64 %0, {%1, %2};" : "=l"(r) : "f"(lo), "f"(hi));
    return r;
}
__device__ __forceinline__ void fma2(unsigned long long& d, unsigned long long a,
                                     unsigned long long b) {
    asm("fma.rn.f32x2 %0, %1, %2, %0;" : "+l"(d) : "l"(a), "l"(b));
}
__device__ __forceinline__ float2 upk2(unsigned long long v) {
    float2 r;
    asm("mov.b64 {%0, %1}, %2;" : "=f"(r.x), "=f"(r.y) : "l"(v));
    return r;
}

// ---------------- cp.async helpers ----------------------------------------------
__device__ __forceinline__ void cpa16(void* dst, const void* src) {
    unsigned saddr = (unsigned)__cvta_generic_to_shared(dst);
    asm volatile("cp.async.cg.shared.global [%0], [%1], 16;" ::"r"(saddr), "l"(src));
}
__device__ __forceinline__ void cpa_commit() {
    asm volatile("cp.async.commit_group;" ::: "memory");
}
__device__ __forceinline__ void cpa_wait_all() {
    asm volatile("cp.async.wait_group 0;" ::: "memory");
}

// =================================================================================
// wqt: transpose Wq [256x256] -> g_WqT.  grid (8,8), 256 threads, 32x32 tiles.
// =================================================================================
__global__ __launch_bounds__(256) void wqt_kernel(const float* __restrict__ W) {
    __shared__ float t[32][33];
    const int bx = blockIdx.x << 5, by = blockIdx.y << 5;
    const int lx = threadIdx.x & 31, ly4 = (threadIdx.x >> 5) << 2;
#pragma unroll
    for (int i = 0; i < 4; i++)
        t[ly4 + i][lx] = W[(by + ly4 + i) * 256 + bx + lx];
    __syncthreads();
#pragma unroll
    for (int i = 0; i < 4; i++)
        g_WqT[(bx + ly4 + i) * 256 + by + lx] = t[lx][ly4 + i];
}

// =================================================================================
// rowgemm (k/v prep only — tiny): C[64 x 256] = A_tile @ W^T
// MODE 1: k  -> row stats, centered TRANSPOSED to g_kcT, g_km/g_kv
// MODE 2: v  -> plain row-major store to g_vmat
// =================================================================================
template <int MODE>
__global__ __launch_bounds__(256, 2) void rowgemm_kernel(const float* __restrict__ A,
                                                         const float* __restrict__ W) {
    __shared__ float As[16][68];    // As[kk][row]
    __shared__ float Bs[16][260];   // Bs[kk][col]

    const int tid = threadIdx.x;
    const int n0  = blockIdx.x * 64;
    const int tr  = tid >> 5;   // 0..7
    const int tc  = tid & 31;   // 0..31

    unsigned long long accp[8][4];
#pragma unroll
    for (int i = 0; i < 8; i++)
#pragma unroll
        for (int j = 0; j < 4; j++) accp[i][j] = 0ull;

    for (int k0 = 0; k0 < 256; k0 += 16) {
        {   // A tile 64x16 (transpose into smem)
            int r = tid >> 2;
            int c = (tid & 3) << 2;
            float4 v = *(const float4*)&A[(n0 + r) * 256 + k0 + c];
            As[c + 0][r] = v.x; As[c + 1][r] = v.y; As[c + 2][r] = v.z; As[c + 3][r] = v.w;
        }
#pragma unroll
        for (int it = 0; it < 4; it++) {   // W tile 256x16 (transpose into smem)
            int fid = tid + (it << 8);
            int j = fid >> 2;
            int c = (fid & 3) << 2;
            float4 v = *(const float4*)&W[j * 256 + k0 + c];
            Bs[c + 0][j] = v.x; Bs[c + 1][j] = v.y; Bs[c + 2][j] = v.z; Bs[c + 3][j] = v.w;
        }
        __syncthreads();
#pragma unroll
        for (int kk = 0; kk < 16; kk++) {
            float4 a0 = *(const float4*)&As[kk][tr * 4];
            float4 a1 = *(const float4*)&As[kk][32 + tr * 4];
            ulonglong2 b0 = *(const ulonglong2*)(const void*)&Bs[kk][tc * 4];
            ulonglong2 b1 = *(const ulonglong2*)(const void*)&Bs[kk][128 + tc * 4];
            unsigned long long ap[8] = {pk2(a0.x, a0.x), pk2(a0.y, a0.y), pk2(a0.z, a0.z),
                                        pk2(a0.w, a0.w), pk2(a1.x, a1.x), pk2(a1.y, a1.y),
                                        pk2(a1.z, a1.z), pk2(a1.w, a1.w)};
            unsigned long long bv[4] = {b0.x, b0.y, b1.x, b1.y};
#pragma unroll
            for (int i = 0; i < 8; i++)
#pragma unroll
                for (int j = 0; j < 4; j++) fma2(accp[i][j], ap[i], bv[j]);
        }
        __syncthreads();
    }

    float acc[8][8];
#pragma unroll
    for (int i = 0; i < 8; i++)
#pragma unroll
        for (int j2 = 0; j2 < 4; j2++) {
            float2 u = upk2(accp[i][j2]);
            acc[i][2 * j2 + 0] = u.x;
            acc[i][2 * j2 + 1] = u.y;
        }

#pragma unroll
    for (int i = 0; i < 8; i++) {
        const int row = n0 + tr * 4 + (i & 3) + ((i >> 2) << 5);
        if (MODE == 2) {
            *(float4*)&g_vmat[row * 256 + tc * 4] =
                make_float4(acc[i][0], acc[i][1], acc[i][2], acc[i][3]);
            *(float4*)&g_vmat[row * 256 + 128 + tc * 4] =
                make_float4(acc[i][4], acc[i][5], acc[i][6], acc[i][7]);
        } else {
            float s = 0.f, ss = 0.f;
#pragma unroll
            for (int j = 0; j < 8; j++) { s += acc[i][j]; ss += acc[i][j] * acc[i][j]; }
#pragma unroll
            for (int o = 16; o > 0; o >>= 1) {
                s  += __shfl_xor_sync(0xffffffffu, s, o);
                ss += __shfl_xor_sync(0xffffffffu, ss, o);
            }
            const float mean = s * (1.0f / 256.0f);
            const float var  = (ss - 256.0f * mean * mean) * (1.0f / 255.0f);
            if (tc == 0) { g_km[row] = mean; g_kv[row] = var; }
#pragma unroll
            for (int j = 0; j < 8; j++) {
                const int col = tc * 4 + (j & 3) + ((j >> 2) << 7);
                g_kcT[col * 1024 + row] = acc[i][j] - mean;
            }
        }
    }
}

// =================================================================================
// q_kernel: C[32n x 256j] = x_tile @ WqT.  grid 2048 (6.9 waves), 256 threads,
// micro 4x8 -> 16 acc u64, 1 float4 A-staging -> ~90 regs (scheduling slack).
// B = g_WqT verbatim cp.async. Outputs qm/qv + RAW q transposed to g_qT.
// =================================================================================
#define QA_STR 36
#define QB_STR 260
#define QA_BUF (32 * QA_STR)          // 1152 floats
#define QB_BUF (32 * QB_STR)          // 8320 floats
#define Q_SMEM_BYTES ((2 * QA_BUF + 2 * QB_BUF) * 4)   // 75776
#define TS_STR 33                     // Ts[256][33] = 8448 floats, aliases B bufs

__device__ __forceinline__ void q_lda(float4& av, const float* __restrict__ x,
                                      int n0, int k0, int tid) {
    const int r = tid >> 3, c = (tid & 7) << 2;
    av = *(const float4*)&x[(n0 + r) * 256 + k0 + c];
}
__device__ __forceinline__ void q_sts(const float4 av, float* As, int tid) {
    const int r = tid >> 3, c = (tid & 7) << 2;
    As[(c + 0) * QA_STR + r] = av.x; As[(c + 1) * QA_STR + r] = av.y;
    As[(c + 2) * QA_STR + r] = av.z; As[(c + 3) * QA_STR + r] = av.w;
}
__device__ __forceinline__ void q_ldb(float* Bs, int k0, int tid) {
#pragma unroll
    for (int it = 0; it < 8; it++) {   // 32 rows x 256 floats verbatim
        int ch = tid + (it << 8);
        int rr = ch >> 6, cc = (ch & 63) << 2;
        cpa16(&Bs[rr * QB_STR + cc], &g_WqT[(k0 + rr) * 256 + cc]);
    }
    cpa_commit();
}
template <int K0, int K1>
__device__ __forceinline__ void q_mma(const float* __restrict__ As,
                                      const float* __restrict__ Bs, int tr, int tc,
                                      unsigned long long accp[4][4]) {
#pragma unroll
    for (int kk = K0; kk < K1; kk++) {
        float4 a = *(const float4*)&As[kk * QA_STR + tr * 4];
        ulonglong2 b0 = *(const ulonglong2*)(const void*)&Bs[kk * QB_STR + tc * 4];
        ulonglong2 b1 = *(const ulonglong2*)(const void*)&Bs[kk * QB_STR + 128 + tc * 4];
        unsigned long long ap[4] = {pk2(a.x, a.x), pk2(a.y, a.y), pk2(a.z, a.z),
                                    pk2(a.w, a.w)};
        unsigned long long bv[4] = {b0.x, b0.y, b1.x, b1.y};
#pragma unroll
        for (int i = 0; i < 4; i++)
#pragma unroll
            for (int j = 0; j < 4; j++) fma2(accp[i][j], ap[i], bv[j]);
    }
}

__global__ __launch_bounds__(256, 2) void q_kernel(const float* __restrict__ x) {
    extern __shared__ float sm[];
    float* Asm[2] = {sm, sm + QA_BUF};
    float* Bsm[2] = {sm + 2 * QA_BUF, sm + 2 * QA_BUF + QB_BUF};
    float* Ts     = sm + 2 * QA_BUF;            // alias over B bufs (post-loop)

    const int tid = threadIdx.x;
    const int n0  = blockIdx.x * 32;
    const int tr  = tid >> 5;   // 0..7  (4 rows each -> 32 rows)
    const int tc  = tid & 31;   // 0..31 (8 cols each -> 256 cols)

    unsigned long long accp[4][4];
#pragma unroll
    for (int i = 0; i < 4; i++)
#pragma unroll
        for (int j = 0; j < 4; j++) accp[i][j] = 0ull;

    float4 av;
    q_lda(av, x, n0, 0, tid);
    q_ldb(Bsm[0], 0, tid);
    q_sts(av, Asm[0], tid);
    cpa_wait_all();
    __syncthreads();

#pragma unroll 1
    for (int t = 0; t < 8; t++) {
        const bool more = (t + 1 < 8);
        if (more) {
            q_ldb(Bsm[(t + 1) & 1], (t + 1) * 32, tid);
            q_lda(av, x, n0, (t + 1) * 32, tid);
        }
        q_mma<0, 16>(Asm[t & 1], Bsm[t & 1], tr, tc, accp);
        if (more) q_sts(av, Asm[(t + 1) & 1], tid);
        q_mma<16, 32>(Asm[t & 1], Bsm[t & 1], tr, tc, accp);
        if (more) cpa_wait_all();
        __syncthreads();
    }

    float acc[4][8];
#pragma unroll
    for (int i = 0; i < 4; i++)
#pragma unroll
        for (int j2 = 0; j2 < 4; j2++) {
            float2 u = upk2(accp[i][j2]);
            acc[i][2 * j2 + 0] = u.x;
            acc[i][2 * j2 + 1] = u.y;
        }

#pragma unroll
    for (int i = 0; i < 4; i++) {
        const int rloc = tr * 4 + i;           // 0..31
        const int row  = n0 + rloc;
        float s = 0.f, ss = 0.f;
#pragma unroll
        for (int j = 0; j < 8; j++) { s += acc[i][j]; ss += acc[i][j] * acc[i][j]; }
#pragma unroll
        for (int o = 16; o > 0; o >>= 1) {
            s  += __shfl_xor_sync(0xffffffffu, s, o);
            ss += __shfl_xor_sync(0xffffffffu, ss, o);
        }
        const float mean = s * (1.0f / 256.0f);
        const float var  = (ss - 256.0f * mean * mean) * (1.0f / 255.0f);
        if (tc == 0) { g_qm[row] = mean; g_qv[row] = var; }
        // RAW q into transpose buffer (cov = q . kc exact: sum(kc)==0)
#pragma unroll
        for (int j = 0; j < 8; j++) {
            const int f = tc * 4 + (j & 3) + ((j >> 2) << 7);
            Ts[f * TS_STR + rloc] = acc[i][j];
        }
    }

    __syncthreads();
    // coalesced transposed write: thread tid owns feature f=tid
    const float* src = &Ts[tid * TS_STR];
    float* dst = &g_qT[(size_t)tid * NROWS + n0];
#pragma unroll
    for (int r = 0; r < 32; r += 4)
        *(float4*)&dst[r] = make_float4(src[r], src[r + 1], src[r + 2], src[r + 3]);
}

// =================================================================================
// 128x128x(BK=32) tile engine (ssim) — both operands verbatim K-major via cp.async.
// =================================================================================
#define T_STR 132
#define T_BUF (32 * T_STR)            // 4224 floats per buffer
#define SMEM_BYTES (4 * T_BUF * 4)    // 67584 bytes

__device__ __forceinline__ void ld_tile(float* dst, const float* __restrict__ src,
                                        size_t row_stride, int tid) {
#pragma unroll
    for (int it = 0; it < 4; it++) {   // 32 rows x 128 floats, verbatim
        int ch = tid + (it << 8);
        int rr = ch >> 5, cc = (ch & 31) << 2;
        cpa16(&dst[rr * T_STR + cc], &src[(size_t)rr * row_stride + cc]);
    }
}

__device__ __forceinline__ void tile_mma(const float* __restrict__ As,
                                         const float* __restrict__ Bs, int tr, int tc,
                                         unsigned long long accp[8][4]) {
#pragma unroll
    for (int kk = 0; kk < 32; kk++) {
        float4 a0 = *(const float4*)&As[kk * T_STR + tr * 4];
        float4 a1 = *(const float4*)&As[kk * T_STR + 64 + tr * 4];
        ulonglong2 b0 = *(const ulonglong2*)(const void*)&Bs[kk * T_STR + tc * 4];
        ulonglong2 b1 = *(const ulonglong2*)(const void*)&Bs[kk * T_STR + 64 + tc * 4];
        unsigned long long ap[8] = {pk2(a0.x, a0.x), pk2(a0.y, a0.y), pk2(a0.z, a0.z),
                                    pk2(a0.w, a0.w), pk2(a1.x, a1.x), pk2(a1.y, a1.y),
                                    pk2(a1.z, a1.z), pk2(a1.w, a1.w)};
        unsigned long long bv[4] = {b0.x, b0.y, b1.x, b1.y};
#pragma unroll
        for (int i = 0; i < 8; i++)
#pragma unroll
            for (int j = 0; j < 4; j++) fma2(accp[i][j], ap[i], bv[j]);
    }
}

// =================================================================================
// ssimT: ST[m, n] = exp(ssim);  A = g_kcT (verbatim), B = g_qT (verbatim).
// cov = kc . q / 255 (raw q: mean term vanishes). Writes per-m-block column sums.
// =================================================================================
__global__ __launch_bounds__(256, 2) void ssim_kernel() {
    extern __shared__ float sm[];
    float* Asm[2] = {sm, sm + T_BUF};
    float* Bsm[2] = {sm + 2 * T_BUF, sm + 3 * T_BUF};

    const int tid = threadIdx.x;
    const int n0 = blockIdx.x << 7;
    const int m0 = blockIdx.y << 7;
    const int tr = tid >> 4;
    const int tc = tid & 15;

    unsigned long long accp[8][4];
#pragma unroll
    for (int i = 0; i < 8; i++)
#pragma unroll
        for (int j = 0; j < 4; j++) accp[i][j] = 0ull;

    ld_tile(Asm[0], &g_kcT[m0], 1024, tid);
    ld_tile(Bsm[0], &g_qT[n0], NROWS, tid);
    cpa_commit();
    cpa_wait_all();
    __syncthreads();

#pragma unroll 1
    for (int t = 0; t < 8; t++) {
        const bool more = (t + 1 < 8);
        if (more) {
            ld_tile(Asm[(t + 1) & 1], &g_kcT[(t + 1) * 32 * 1024 + m0], 1024, tid);
            ld_tile(Bsm[(t + 1) & 1], &g_qT[(size_t)(t + 1) * 32 * NROWS + n0], NROWS,
                    tid);
            cpa_commit();
        }
        tile_mma(Asm[t & 1], Bsm[t & 1], tr, tc, accp);
        if (more) cpa_wait_all();
        __syncthreads();
    }

    float acc[8][8];
#pragma unroll
    for (int i = 0; i < 8; i++)
#pragma unroll
        for (int j2 = 0; j2 < 4; j2++) {
            float2 u = upk2(accp[i][j2]);
            acc[i][2 * j2 + 0] = u.x;
            acc[i][2 * j2 + 1] = u.y;
        }

    const float C1f = 0.01f, C2f = 0.03f, EPSf = 1e-8f, INV255 = 1.0f / 255.0f;

    float km[8], kv[8], qm[8], qv[8];
#pragma unroll
    for (int i = 0; i < 8; i++) {   // A side = m
        const int mrow = m0 + tr * 4 + (i & 3) + ((i >> 2) << 6);
        km[i] = g_km[mrow];
        kv[i] = g_kv[mrow];
    }
#pragma unroll
    for (int j = 0; j < 8; j++) {   // B side = n
        const int ncol = n0 + tc * 4 + (j & 3) + ((j >> 2) << 6);
        qm[j] = g_qm[ncol];
        qv[j] = g_qv[ncol];
    }

    float colp[8];
#pragma unroll
    for (int j = 0; j < 8; j++) colp[j] = 0.f;

#pragma unroll
    for (int i = 0; i < 8; i++) {
        const int mrow = m0 + tr * 4 + (i & 3) + ((i >> 2) << 6);
        float p[8];
#pragma unroll
        for (int j = 0; j < 8; j++) {
            const float cov = acc[i][j] * INV255;
            const float num = (2.0f * qm[j] * km[i] + C1f) * (2.0f * cov + C2f);
            const float den =
                (qm[j] * qm[j] + km[i] * km[i] + C1f) * (qv[j] + kv[i] + C2f) + EPSf;
            p[j] = __expf(__fdividef(num, den));  // ssim bounded: exp safe w/o max
            colp[j] += p[j];
        }
        *(float4*)&g_ST[(size_t)mrow * NROWS + n0 + tc * 4] =
            make_float4(p[0], p[1], p[2], p[3]);
        *(float4*)&g_ST[(size_t)mrow * NROWS + n0 + 64 + tc * 4] =
            make_float4(p[4], p[5], p[6], p[7]);
    }

    // column-sum over the 128 m's of this block: pair-reduce tr (xor16), then smem
#pragma unroll
    for (int j = 0; j < 8; j++)
        colp[j] += __shfl_xor_sync(0xffffffffu, colp[j], 16);
    float* red = sm;                       // reuse tile smem: red[8][128]
    const int warp = tid >> 5, lane = tid & 31;
    if (lane < 16) {
#pragma unroll
        for (int j = 0; j < 8; j++)
            red[warp * 128 + tc * 4 + (j & 3) + ((j >> 2) << 6)] = colp[j];
    }
    __syncthreads();
    if (tid < 128) {
        float s = 0.f;
#pragma unroll
        for (int w = 0; w < 8; w++) s += red[w * 128 + tid];
        g_psum[blockIdx.y * NROWS + n0 + tid] = s;    // unique writer: deterministic
    }
}

// =================================================================================
// out32: out[32n x 256f] = (P @ v) / rowsum.  grid 2048 (6.9 waves), 256 threads,
// micro 4x8 -> 16 acc u64. A = g_ST n-slice (verbatim, read once), B = g_vmat.
// =================================================================================
#define OA_STR 36
#define OB_STR 260
#define OA_BUF (32 * OA_STR)          // 1152
#define OB_BUF (32 * OB_STR)          // 8320
#define O_SMEM_BYTES ((2 * OA_BUF + 2 * OB_BUF) * 4)   // 75776

__device__ __forceinline__ void o_lda(float* dst, int t, int n0, int tid) {
    const int rr = tid >> 3, cc = (tid & 7) << 2;   // 32 m-rows x 32 n-cols
    cpa16(&dst[rr * OA_STR + cc], &g_ST[(size_t)(t * 32 + rr) * NROWS + n0 + cc]);
}
__device__ __forceinline__ void o_ldb(float* dst, int t, int tid) {
#pragma unroll
    for (int it = 0; it < 8; it++) {   // 32 m-rows x 256 f-cols
        int ch = tid + (it << 8);
        int rr = ch >> 6, cc = (ch & 63) << 2;
        cpa16(&dst[rr * OB_STR + cc], &g_vmat[(t * 32 + rr) * 256 + cc]);
    }
}

__global__ __launch_bounds__(256, 2) void out_kernel(float* __restrict__ out) {
    extern __shared__ float sm[];
    float* Asm[2] = {sm, sm + OA_BUF};
    float* Bsm[2] = {sm + 2 * OA_BUF, sm + 2 * OA_BUF + OB_BUF};

    const int tid = threadIdx.x;
    const int n0 = blockIdx.x << 5;
    const int tr = tid >> 5;   // 0..7  (4 n-rows each)
    const int tc = tid & 31;   // 0..31 (8 f-cols each)

    unsigned long long accp[4][4];
#pragma unroll
    for (int i = 0; i < 4; i++)
#pragma unroll
        for (int j = 0; j < 4; j++) accp[i][j] = 0ull;

    o_lda(Asm[0], 0, n0, tid);
    o_ldb(Bsm[0], 0, tid);
    cpa_commit();
    cpa_wait_all();
    __syncthreads();

#pragma unroll 1
    for (int t = 0; t < 32; t++) {
        const bool more = (t + 1 < 32);
        if (more) {
            o_lda(Asm[(t + 1) & 1], t + 1, n0, tid);
            o_ldb(Bsm[(t + 1) & 1], t + 1, tid);
            cpa_commit();
        }
        const float* As = Asm[t & 1];
        const float* Bs = Bsm[t & 1];
#pragma unroll
        for (int kk = 0; kk < 32; kk++) {
            float4 a = *(const float4*)&As[kk * OA_STR + tr * 4];
            ulonglong2 b0 = *(const ulonglong2*)(const void*)&Bs[kk * OB_STR + tc * 4];
            ulonglong2 b1 =
                *(const ulonglong2*)(const void*)&Bs[kk * OB_STR + 128 + tc * 4];
            unsigned long long ap[4] = {pk2(a.x, a.x), pk2(a.y, a.y), pk2(a.z, a.z),
                                        pk2(a.w, a.w)};
            unsigned long long bv[4] = {b0.x, b0.y, b1.x, b1.y};
#pragma unroll
            for (int i = 0; i < 4; i++)
#pragma unroll
                for (int j = 0; j < 4; j++) fma2(accp[i][j], ap[i], bv[j]);
        }
        if (more) cpa_wait_all();
        __syncthreads();
    }

#pragma unroll
    for (int i = 0; i < 4; i++) {
        const int row = n0 + tr * 4 + i;
        float s = 0.f;
#pragma unroll
        for (int b = 0; b < 8; b++) s += g_psum[b * NROWS + row];
        const float inv = 1.0f / s;
        float2 u0 = upk2(accp[i][0]);
        float2 u1 = upk2(accp[i][1]);
        float2 u2 = upk2(accp[i][2]);
        float2 u3 = upk2(accp[i][3]);
        *(float4*)&out[row * 256 + tc * 4] =
            make_float4(u0.x * inv, u0.y * inv, u1.x * inv, u1.y * inv);
        *(float4*)&out[row * 256 + 128 + tc * 4] =
            make_float4(u2.x * inv, u2.y * inv, u3.x * inv, u3.y * inv);
    }
}

// =================================================================================
extern "C" void kernel_launch(void* const* d_in, const int* in_sizes, int n_in,
                              void* d_out, int out_size) {
    (void)in_sizes; (void)n_in; (void)out_size;
    const float* x   = (const float*)d_in[0];   // [8192, 8, 256] -> [65536, 256]
    const float* mem = (const float*)d_in[1];   // [1024, 16, 16] -> [1024, 256]
    const float* Wq  = (const float*)d_in[2];   // [256, 256]
    const float* Wk  = (const float*)d_in[3];
    const float* Wv  = (const float*)d_in[4];
    float* out = (float*)d_out;

    cudaFuncSetAttribute(q_kernel, cudaFuncAttributeMaxDynamicSharedMemorySize,
                         Q_SMEM_BYTES);
    cudaFuncSetAttribute(ssim_kernel, cudaFuncAttributeMaxDynamicSharedMemorySize,
                         SMEM_BYTES);
    cudaFuncSetAttribute(out_kernel, cudaFuncAttributeMaxDynamicSharedMemorySize,
                         O_SMEM_BYTES);

    wqt_kernel<<<dim3(8, 8), 256>>>(Wq);                   // WqT
    rowgemm_kernel<1><<<16, 256>>>(mem, Wk);               // k -> centered kcT + km/kv
    rowgemm_kernel<2><<<16, 256>>>(mem, Wv);               // v
    q_kernel<<<2048, 256, Q_SMEM_BYTES>>>(x);              // q -> qT + qm/qv
    ssim_kernel<<<dim3(512, 8), 256, SMEM_BYTES>>>();      // ST = exp(ssim), psum
    out_kernel<<<2048, 256, O_SMEM_BYTES>>>(out);          // out = (P @ v)/rowsum
}

// round 16
// speedup vs baseline: 1.1971x; 1.1971x over previous
#include <cuda_runtime.h>

#define NROWS 65536   // N_TOKENS * BATCH
#define FDIM  256     // HW
#define MDIM  1024    // MEM_DIM

// ---------------- scratch (static device globals; no allocation) ----------------
__device__ float g_qT[FDIM * NROWS];            // q TRANSPOSED [F, N]            (64 MB)
__device__ float g_qm[NROWS];
__device__ float g_qv[NROWS];
__device__ float g_kcT[FDIM * MDIM];            // centered k, TRANSPOSED [F, M]  (1 MB)
__device__ float g_vmat[MDIM * FDIM];           // v, row-major [M, F]            (1 MB)
__device__ float g_km[MDIM];
__device__ float g_kv[MDIM];
__device__ float g_WqT[FDIM * FDIM];            // Wq transposed [h, j]           (256 KB)
__device__ float g_ST[(size_t)MDIM * NROWS];    // p = exp(ssim) TRANSPOSED [M,N] (256 MB)
__device__ float g_psum[8 * NROWS];             // per-m-block partial col sums   (2 MB)

// ---------------- packed f32x2 helpers (full-rate FP32 on sm_103a) --------------
__device__ __forceinline__ unsigned long long pk2(float lo, float hi) {
    unsigned long long r;
    asm("mov.b64 %0, {%1, %2};" : "=l"(r) : "f"(lo), "f"(hi));
    return r;
}
__device__ __forceinline__ void fma2(unsigned long long& d, unsigned long long a,
                                     unsigned long long b) {
    asm("fma.rn.f32x2 %0, %1, %2, %0;" : "+l"(d) : "l"(a), "l"(b));
}
__device__ __forceinline__ float2 upk2(unsigned long long v) {
    float2 r;
    asm("mov.b64 {%0, %1}, %2;" : "=f"(r.x), "=f"(r.y) : "l"(v));
    return r;
}

// ---------------- cp.async helpers ----------------------------------------------
__device__ __forceinline__ void cpa16(void* dst, const void* src) {
    unsigned saddr = (unsigned)__cvta_generic_to_shared(dst);
    asm volatile("cp.async.cg.shared.global [%0], [%1], 16;" ::"r"(saddr), "l"(src));
}
__device__ __forceinline__ void cpa_commit() {
    asm volatile("cp.async.commit_group;" ::: "memory");
}
__device__ __forceinline__ void cpa_wait_all() {
    asm volatile("cp.async.wait_group 0;" ::: "memory");
}

// =================================================================================
// wqt: transpose Wq [256x256] -> g_WqT.  grid (8,8), 256 threads, 32x32 tiles.
// =================================================================================
__global__ __launch_bounds__(256) void wqt_kernel(const float* __restrict__ W) {
    __shared__ float t[32][33];
    const int bx = blockIdx.x << 5, by = blockIdx.y << 5;
    const int lx = threadIdx.x & 31, ly4 = (threadIdx.x >> 5) << 2;
#pragma unroll
    for (int i = 0; i < 4; i++)
        t[ly4 + i][lx] = W[(by + ly4 + i) * 256 + bx + lx];
    __syncthreads();
#pragma unroll
    for (int i = 0; i < 4; i++)
        g_WqT[(bx + ly4 + i) * 256 + by + lx] = t[lx][ly4 + i];
}

// =================================================================================
// rowgemm (k/v prep only — tiny): C[64 x 256] = A_tile @ W^T
// MODE 1: k  -> row stats, centered TRANSPOSED to g_kcT, g_km/g_kv
// MODE 2: v  -> plain row-major store to g_vmat
// =================================================================================
template <int MODE>
__global__ __launch_bounds__(256, 2) void rowgemm_kernel(const float* __restrict__ A,
                                                         const float* __restrict__ W) {
    __shared__ float As[16][68];    // As[kk][row]
    __shared__ float Bs[16][260];   // Bs[kk][col]

    const int tid = threadIdx.x;
    const int n0  = blockIdx.x * 64;
    const int tr  = tid >> 5;   // 0..7
    const int tc  = tid & 31;   // 0..31

    unsigned long long accp[8][4];
#pragma unroll
    for (int i = 0; i < 8; i++)
#pragma unroll
        for (int j = 0; j < 4; j++) accp[i][j] = 0ull;

    for (int k0 = 0; k0 < 256; k0 += 16) {
        {   // A tile 64x16 (transpose into smem)
            int r = tid >> 2;
            int c = (tid & 3) << 2;
            float4 v = *(const float4*)&A[(n0 + r) * 256 + k0 + c];
            As[c + 0][r] = v.x; As[c + 1][r] = v.y; As[c + 2][r] = v.z; As[c + 3][r] = v.w;
        }
#pragma unroll
        for (int it = 0; it < 4; it++) {   // W tile 256x16 (transpose into smem)
            int fid = tid + (it << 8);
            int j = fid >> 2;
            int c = (fid & 3) << 2;
            float4 v = *(const float4*)&W[j * 256 + k0 + c];
            Bs[c + 0][j] = v.x; Bs[c + 1][j] = v.y; Bs[c + 2][j] = v.z; Bs[c + 3][j] = v.w;
        }
        __syncthreads();
#pragma unroll
        for (int kk = 0; kk < 16; kk++) {
            float4 a0 = *(const float4*)&As[kk][tr * 4];
            float4 a1 = *(const float4*)&As[kk][32 + tr * 4];
            ulonglong2 b0 = *(const ulonglong2*)(const void*)&Bs[kk][tc * 4];
            ulonglong2 b1 = *(const ulonglong2*)(const void*)&Bs[kk][128 + tc * 4];
            unsigned long long ap[8] = {pk2(a0.x, a0.x), pk2(a0.y, a0.y), pk2(a0.z, a0.z),
                                        pk2(a0.w, a0.w), pk2(a1.x, a1.x), pk2(a1.y, a1.y),
                                        pk2(a1.z, a1.z), pk2(a1.w, a1.w)};
            unsigned long long bv[4] = {b0.x, b0.y, b1.x, b1.y};
#pragma unroll
            for (int i = 0; i < 8; i++)
#pragma unroll
                for (int j = 0; j < 4; j++) fma2(accp[i][j], ap[i], bv[j]);
        }
        __syncthreads();
    }

    float acc[8][8];
#pragma unroll
    for (int i = 0; i < 8; i++)
#pragma unroll
        for (int j2 = 0; j2 < 4; j2++) {
            float2 u = upk2(accp[i][j2]);
            acc[i][2 * j2 + 0] = u.x;
            acc[i][2 * j2 + 1] = u.y;
        }

#pragma unroll
    for (int i = 0; i < 8; i++) {
        const int row = n0 + tr * 4 + (i & 3) + ((i >> 2) << 5);
        if (MODE == 2) {
            *(float4*)&g_vmat[row * 256 + tc * 4] =
                make_float4(acc[i][0], acc[i][1], acc[i][2], acc[i][3]);
            *(float4*)&g_vmat[row * 256 + 128 + tc * 4] =
                make_float4(acc[i][4], acc[i][5], acc[i][6], acc[i][7]);
        } else {
            float s = 0.f, ss = 0.f;
#pragma unroll
            for (int j = 0; j < 8; j++) { s += acc[i][j]; ss += acc[i][j] * acc[i][j]; }
#pragma unroll
            for (int o = 16; o > 0; o >>= 1) {
                s  += __shfl_xor_sync(0xffffffffu, s, o);
                ss += __shfl_xor_sync(0xffffffffu, ss, o);
            }
            const float mean = s * (1.0f / 256.0f);
            const float var  = (ss - 256.0f * mean * mean) * (1.0f / 255.0f);
            if (tc == 0) { g_km[row] = mean; g_kv[row] = var; }
#pragma unroll
            for (int j = 0; j < 8; j++) {
                const int col = tc * 4 + (j & 3) + ((j >> 2) << 7);
                g_kcT[col * 1024 + row] = acc[i][j] - mean;
            }
        }
    }
}

// =================================================================================
// q_kernel: C[64n x 256j] = x_tile @ WqT, single-barrier cp.async pipeline.
//   B = g_WqT (K-major, verbatim cp.async).  A = x tile, LDG->regs, STS-transpose
//   tucked between the two mma halves.  8x8 micro-tile (PROVEN floor shape).
// Outputs: row stats (qm/qv) + RAW q transposed to g_qT via smem Ts (aliased
// over the B buffers after the K loop).
// =================================================================================
#define QA_STR 68
#define QB_STR 260
#define QA_BUF (32 * QA_STR)          // 2176 floats
#define QB_BUF (32 * QB_STR)          // 8320 floats
#define Q_SMEM_FLOATS (2 * QA_BUF + 2 * QB_BUF)   // 20992
#define Q_SMEM_BYTES (Q_SMEM_FLOATS * 4)          // 83968
#define TS_STR 65                     // Ts[256][65] = 16640 floats, aliases B bufs

__device__ __forceinline__ void q_lda(float4 av[2], const float* __restrict__ x,
                                      int n0, int k0, int tid) {
    const int r = tid >> 2, c = (tid & 3) << 3;
    av[0] = *(const float4*)&x[(n0 + r) * 256 + k0 + c];
    av[1] = *(const float4*)&x[(n0 + r) * 256 + k0 + c + 4];
}
__device__ __forceinline__ void q_sts(const float4 av[2], float* As, int tid) {
    const int r = tid >> 2, c = (tid & 3) << 3;
    As[(c + 0) * QA_STR + r] = av[0].x; As[(c + 1) * QA_STR + r] = av[0].y;
    As[(c + 2) * QA_STR + r] = av[0].z; As[(c + 3) * QA_STR + r] = av[0].w;
    As[(c + 4) * QA_STR + r] = av[1].x; As[(c + 5) * QA_STR + r] = av[1].y;
    As[(c + 6) * QA_STR + r] = av[1].z; As[(c + 7) * QA_STR + r] = av[1].w;
}
__device__ __forceinline__ void q_ldb(float* Bs, int k0, int tid) {
#pragma unroll
    for (int it = 0; it < 8; it++) {   // 32 rows x 256 floats verbatim
        int ch = tid + (it << 8);
        int rr = ch >> 6, cc = (ch & 63) << 2;
        cpa16(&Bs[rr * QB_STR + cc], &g_WqT[(k0 + rr) * 256 + cc]);
    }
    cpa_commit();
}
template <int K0, int K1>
__device__ __forceinline__ void q_mma(const float* __restrict__ As,
                                      const float* __restrict__ Bs, int tr, int tc,
                                      unsigned long long accp[8][4]) {
#pragma unroll
    for (int kk = K0; kk < K1; kk++) {
        float4 a0 = *(const float4*)&As[kk * QA_STR + tr * 4];
        float4 a1 = *(const float4*)&As[kk * QA_STR + 32 + tr * 4];
        ulonglong2 b0 = *(const ulonglong2*)(const void*)&Bs[kk * QB_STR + tc * 4];
        ulonglong2 b1 = *(const ulonglong2*)(const void*)&Bs[kk * QB_STR + 128 + tc * 4];
        unsigned long long ap[8] = {pk2(a0.x, a0.x), pk2(a0.y, a0.y), pk2(a0.z, a0.z),
                                    pk2(a0.w, a0.w), pk2(a1.x, a1.x), pk2(a1.y, a1.y),
                                    pk2(a1.z, a1.z), pk2(a1.w, a1.w)};
        unsigned long long bv[4] = {b0.x, b0.y, b1.x, b1.y};
#pragma unroll
        for (int i = 0; i < 8; i++)
#pragma unroll
            for (int j = 0; j < 4; j++) fma2(accp[i][j], ap[i], bv[j]);
    }
}

__global__ __launch_bounds__(256, 2) void q_kernel(const float* __restrict__ x) {
    extern __shared__ float sm[];
    float* Asm[2] = {sm, sm + QA_BUF};
    float* Bsm[2] = {sm + 2 * QA_BUF, sm + 2 * QA_BUF + QB_BUF};
    float* Ts     = sm + 2 * QA_BUF;            // alias over B bufs (post-loop)

    const int tid = threadIdx.x;
    const int n0  = blockIdx.x * 64;
    const int tr  = tid >> 5;
    const int tc  = tid & 31;

    unsigned long long accp[8][4];
#pragma unroll
    for (int i = 0; i < 8; i++)
#pragma unroll
        for (int j = 0; j < 4; j++) accp[i][j] = 0ull;

    float4 av[2];
    q_lda(av, x, n0, 0, tid);
    q_ldb(Bsm[0], 0, tid);
    q_sts(av, Asm[0], tid);
    cpa_wait_all();
    __syncthreads();

#pragma unroll 1
    for (int t = 0; t < 8; t++) {
        const bool more = (t + 1 < 8);
        if (more) {
            q_ldb(Bsm[(t + 1) & 1], (t + 1) * 32, tid);
            q_lda(av, x, n0, (t + 1) * 32, tid);
        }
        q_mma<0, 16>(Asm[t & 1], Bsm[t & 1], tr, tc, accp);
        if (more) q_sts(av, Asm[(t + 1) & 1], tid);
        q_mma<16, 32>(Asm[t & 1], Bsm[t & 1], tr, tc, accp);
        if (more) cpa_wait_all();
        __syncthreads();
    }

    float acc[8][8];
#pragma unroll
    for (int i = 0; i < 8; i++)
#pragma unroll
        for (int j2 = 0; j2 < 4; j2++) {
            float2 u = upk2(accp[i][j2]);
            acc[i][2 * j2 + 0] = u.x;
            acc[i][2 * j2 + 1] = u.y;
        }

#pragma unroll
    for (int i = 0; i < 8; i++) {
        const int rloc = tr * 4 + (i & 3) + ((i >> 2) << 5);   // 0..63
        const int row  = n0 + rloc;
        float s = 0.f, ss = 0.f;
#pragma unroll
        for (int j = 0; j < 8; j++) { s += acc[i][j]; ss += acc[i][j] * acc[i][j]; }
#pragma unroll
        for (int o = 16; o > 0; o >>= 1) {
            s  += __shfl_xor_sync(0xffffffffu, s, o);
            ss += __shfl_xor_sync(0xffffffffu, ss, o);
        }
        const float mean = s * (1.0f / 256.0f);
        const float var  = (ss - 256.0f * mean * mean) * (1.0f / 255.0f);
        if (tc == 0) { g_qm[row] = mean; g_qv[row] = var; }
        // RAW q into transpose buffer (cov = q . kc exact: sum(kc)==0)
#pragma unroll
        for (int j = 0; j < 8; j++) {
            const int f = tc * 4 + (j & 3) + ((j >> 2) << 7);
            Ts[f * TS_STR + rloc] = acc[i][j];
        }
    }

    __syncthreads();
    // coalesced transposed write: thread tid owns feature f=tid
    const float* src = &Ts[tid * TS_STR];
    float* dst = &g_qT[(size_t)tid * NROWS + n0];
#pragma unroll
    for (int r = 0; r < 64; r += 4)
        *(float4*)&dst[r] = make_float4(src[r], src[r + 1], src[r + 2], src[r + 3]);
}

// =================================================================================
// 128x128x(BK=32) tile engine (ssim) — both operands verbatim K-major via cp.async.
// =================================================================================
#define T_STR 132
#define T_BUF (32 * T_STR)            // 4224 floats per buffer
#define SMEM_BYTES (4 * T_BUF * 4)    // 67584 bytes

__device__ __forceinline__ void ld_tile(float* dst, const float* __restrict__ src,
                                        size_t row_stride, int tid) {
#pragma unroll
    for (int it = 0; it < 4; it++) {   // 32 rows x 128 floats, verbatim
        int ch = tid + (it << 8);
        int rr = ch >> 5, cc = (ch & 31) << 2;
        cpa16(&dst[rr * T_STR + cc], &src[(size_t)rr * row_stride + cc]);
    }
}

__device__ __forceinline__ void tile_mma(const float* __restrict__ As,
                                         const float* __restrict__ Bs, int tr, int tc,
                                         unsigned long long accp[8][4]) {
#pragma unroll
    for (int kk = 0; kk < 32; kk++) {
        float4 a0 = *(const float4*)&As[kk * T_STR + tr * 4];
        float4 a1 = *(const float4*)&As[kk * T_STR + 64 + tr * 4];
        ulonglong2 b0 = *(const ulonglong2*)(const void*)&Bs[kk * T_STR + tc * 4];
        ulonglong2 b1 = *(const ulonglong2*)(const void*)&Bs[kk * T_STR + 64 + tc * 4];
        unsigned long long ap[8] = {pk2(a0.x, a0.x), pk2(a0.y, a0.y), pk2(a0.z, a0.z),
                                    pk2(a0.w, a0.w), pk2(a1.x, a1.x), pk2(a1.y, a1.y),
                                    pk2(a1.z, a1.z), pk2(a1.w, a1.w)};
        unsigned long long bv[4] = {b0.x, b0.y, b1.x, b1.y};
#pragma unroll
        for (int i = 0; i < 8; i++)
#pragma unroll
            for (int j = 0; j < 4; j++) fma2(accp[i][j], ap[i], bv[j]);
    }
}

// =================================================================================
// ssimT: ST[m, n] = exp(ssim);  A = g_kcT (verbatim), B = g_qT (verbatim).
// cov = kc . q / 255 (raw q: mean term vanishes). Writes per-m-block column sums.
// =================================================================================
__global__ __launch_bounds__(256, 2) void ssim_kernel() {
    extern __shared__ float sm[];
    float* Asm[2] = {sm, sm + T_BUF};
    float* Bsm[2] = {sm + 2 * T_BUF, sm + 3 * T_BUF};

    const int tid = threadIdx.x;
    const int n0 = blockIdx.x << 7;
    const int m0 = blockIdx.y << 7;
    const int tr = tid >> 4;
    const int tc = tid & 15;

    unsigned long long accp[8][4];
#pragma unroll
    for (int i = 0; i < 8; i++)
#pragma unroll
        for (int j = 0; j < 4; j++) accp[i][j] = 0ull;

    ld_tile(Asm[0], &g_kcT[m0], 1024, tid);
    ld_tile(Bsm[0], &g_qT[n0], NROWS, tid);
    cpa_commit();
    cpa_wait_all();
    __syncthreads();

#pragma unroll 1
    for (int t = 0; t < 8; t++) {
        const bool more = (t + 1 < 8);
        if (more) {
            ld_tile(Asm[(t + 1) & 1], &g_kcT[(t + 1) * 32 * 1024 + m0], 1024, tid);
            ld_tile(Bsm[(t + 1) & 1], &g_qT[(size_t)(t + 1) * 32 * NROWS + n0], NROWS,
                    tid);
            cpa_commit();
        }
        tile_mma(Asm[t & 1], Bsm[t & 1], tr, tc, accp);
        if (more) cpa_wait_all();
        __syncthreads();
    }

    float acc[8][8];
#pragma unroll
    for (int i = 0; i < 8; i++)
#pragma unroll
        for (int j2 = 0; j2 < 4; j2++) {
            float2 u = upk2(accp[i][j2]);
            acc[i][2 * j2 + 0] = u.x;
            acc[i][2 * j2 + 1] = u.y;
        }

    const float C1f = 0.01f, C2f = 0.03f, EPSf = 1e-8f, INV255 = 1.0f / 255.0f;

    float km[8], kv[8], qm[8], qv[8];
#pragma unroll
    for (int i = 0; i < 8; i++) {   // A side = m
        const int mrow = m0 + tr * 4 + (i & 3) + ((i >> 2) << 6);
        km[i] = g_km[mrow];
        kv[i] = g_kv[mrow];
    }
#pragma unroll
    for (int j = 0; j < 8; j++) {   // B side = n
        const int ncol = n0 + tc * 4 + (j & 3) + ((j >> 2) << 6);
        qm[j] = g_qm[ncol];
        qv[j] = g_qv[ncol];
    }

    float colp[8];
#pragma unroll
    for (int j = 0; j < 8; j++) colp[j] = 0.f;

#pragma unroll
    for (int i = 0; i < 8; i++) {
        const int mrow = m0 + tr * 4 + (i & 3) + ((i >> 2) << 6);
        float p[8];
#pragma unroll
        for (int j = 0; j < 8; j++) {
            const float cov = acc[i][j] * INV255;
            const float num = (2.0f * qm[j] * km[i] + C1f) * (2.0f * cov + C2f);
            const float den =
                (qm[j] * qm[j] + km[i] * km[i] + C1f) * (qv[j] + kv[i] + C2f) + EPSf;
            p[j] = __expf(__fdividef(num, den));  // ssim bounded: exp safe w/o max
            colp[j] += p[j];
        }
        *(float4*)&g_ST[(size_t)mrow * NROWS + n0 + tc * 4] =
            make_float4(p[0], p[1], p[2], p[3]);
        *(float4*)&g_ST[(size_t)mrow * NROWS + n0 + 64 + tc * 4] =
            make_float4(p[4], p[5], p[6], p[7]);
    }

    // column-sum over the 128 m's of this block: pair-reduce tr (xor16), then smem
#pragma unroll
    for (int j = 0; j < 8; j++)
        colp[j] += __shfl_xor_sync(0xffffffffu, colp[j], 16);
    float* red = sm;                       // reuse tile smem: red[8][128]
    const int warp = tid >> 5, lane = tid & 31;
    if (lane < 16) {
#pragma unroll
        for (int j = 0; j < 8; j++)
            red[warp * 128 + tc * 4 + (j & 3) + ((j >> 2) << 6)] = colp[j];
    }
    __syncthreads();
    if (tid < 128) {
        float s = 0.f;
#pragma unroll
        for (int w = 0; w < 8; w++) s += red[w * 128 + tid];
        g_psum[blockIdx.y * NROWS + n0 + tid] = s;    // unique writer: deterministic
    }
}

// =================================================================================
// out64: out[64n x 256f] = (P @ v) / rowsum.  A = g_ST n-slice (verbatim, read
// once), B = g_vmat (verbatim, L2-resident). 8x8 micro (tr=tid>>5, tc=tid&31).
// =================================================================================
#define OA_STR 68
#define OB_STR 260
#define OA_BUF (32 * OA_STR)          // 2176
#define OB_BUF (32 * OB_STR)          // 8320
#define O_SMEM_BYTES ((2 * OA_BUF + 2 * OB_BUF) * 4)   // 83968

__device__ __forceinline__ void o_lda(float* dst, int t, int n0, int tid) {
#pragma unroll
    for (int it = 0; it < 2; it++) {   // 32 m-rows x 64 n-cols
        int ch = tid + (it << 8);
        int rr = ch >> 4, cc = (ch & 15) << 2;
        cpa16(&dst[rr * OA_STR + cc], &g_ST[(size_t)(t * 32 + rr) * NROWS + n0 + cc]);
    }
}
__device__ __forceinline__ void o_ldb(float* dst, int t, int tid) {
#pragma unroll
    for (int it = 0; it < 8; it++) {   // 32 m-rows x 256 f-cols
        int ch = tid + (it << 8);
        int rr = ch >> 6, cc = (ch & 63) << 2;
        cpa16(&dst[rr * OB_STR + cc], &g_vmat[(t * 32 + rr) * 256 + cc]);
    }
}

__global__ __launch_bounds__(256, 2) void out_kernel(float* __restrict__ out) {
    extern __shared__ float sm[];
    float* Asm[2] = {sm, sm + OA_BUF};
    float* Bsm[2] = {sm + 2 * OA_BUF, sm + 2 * OA_BUF + OB_BUF};

    const int tid = threadIdx.x;
    const int n0 = blockIdx.x << 6;
    const int tr = tid >> 5;
    const int tc = tid & 31;

    unsigned long long accp[8][4];
#pragma unroll
    for (int i = 0; i < 8; i++)
#pragma unroll
        for (int j = 0; j < 4; j++) accp[i][j] = 0ull;

    o_lda(Asm[0], 0, n0, tid);
    o_ldb(Bsm[0], 0, tid);
    cpa_commit();
    cpa_wait_all();
    __syncthreads();

#pragma unroll 1
    for (int t = 0; t < 32; t++) {
        const bool more = (t + 1 < 32);
        if (more) {
            o_lda(Asm[(t + 1) & 1], t + 1, n0, tid);
            o_ldb(Bsm[(t + 1) & 1], t + 1, tid);
            cpa_commit();
        }
        // mma: rows = n (64), cols = f (256)
        const float* As = Asm[t & 1];
        const float* Bs = Bsm[t & 1];
#pragma unroll
        for (int kk = 0; kk < 32; kk++) {
            float4 a0 = *(const float4*)&As[kk * OA_STR + tr * 4];
            float4 a1 = *(const float4*)&As[kk * OA_STR + 32 + tr * 4];
            ulonglong2 b0 = *(const ulonglong2*)(const void*)&Bs[kk * OB_STR + tc * 4];
            ulonglong2 b1 =
                *(const ulonglong2*)(const void*)&Bs[kk * OB_STR + 128 + tc * 4];
            unsigned long long ap[8] = {pk2(a0.x, a0.x), pk2(a0.y, a0.y),
                                        pk2(a0.z, a0.z), pk2(a0.w, a0.w),
                                        pk2(a1.x, a1.x), pk2(a1.y, a1.y),
                                        pk2(a1.z, a1.z), pk2(a1.w, a1.w)};
            unsigned long long bv[4] = {b0.x, b0.y, b1.x, b1.y};
#pragma unroll
            for (int i = 0; i < 8; i++)
#pragma unroll
                for (int j = 0; j < 4; j++) fma2(accp[i][j], ap[i], bv[j]);
        }
        if (more) cpa_wait_all();
        __syncthreads();
    }

#pragma unroll
    for (int i = 0; i < 8; i++) {
        const int row = n0 + tr * 4 + (i & 3) + ((i >> 2) << 5);
        float s = 0.f;
#pragma unroll
        for (int b = 0; b < 8; b++) s += g_psum[b * NROWS + row];
        const float inv = 1.0f / s;
        float2 u0 = upk2(accp[i][0]);
        float2 u1 = upk2(accp[i][1]);
        float2 u2 = upk2(accp[i][2]);
        float2 u3 = upk2(accp[i][3]);
        *(float4*)&out[row * 256 + tc * 4] =
            make_float4(u0.x * inv, u0.y * inv, u1.x * inv, u1.y * inv);
        *(float4*)&out[row * 256 + 128 + tc * 4] =
            make_float4(u2.x * inv, u2.y * inv, u3.x * inv, u3.y * inv);
    }
}

// =================================================================================
extern "C" void kernel_launch(void* const* d_in, const int* in_sizes, int n_in,
                              void* d_out, int out_size) {
    (void)in_sizes; (void)n_in; (void)out_size;
    const float* x   = (const float*)d_in[0];   // [8192, 8, 256] -> [65536, 256]
    const float* mem = (const float*)d_in[1];   // [1024, 16, 16] -> [1024, 256]
    const float* Wq  = (const float*)d_in[2];   // [256, 256]
    const float* Wk  = (const float*)d_in[3];
    const float* Wv  = (const float*)d_in[4];
    float* out = (float*)d_out;

    cudaFuncSetAttribute(q_kernel, cudaFuncAttributeMaxDynamicSharedMemorySize,
                         Q_SMEM_BYTES);
    cudaFuncSetAttribute(ssim_kernel, cudaFuncAttributeMaxDynamicSharedMemorySize,
                         SMEM_BYTES);
    cudaFuncSetAttribute(out_kernel, cudaFuncAttributeMaxDynamicSharedMemorySize,
                         O_SMEM_BYTES);

    wqt_kernel<<<dim3(8, 8), 256>>>(Wq);                   // WqT
    rowgemm_kernel<1><<<16, 256>>>(mem, Wk);               // k -> centered kcT + km/kv
    rowgemm_kernel<2><<<16, 256>>>(mem, Wv);               // v
    q_kernel<<<1024, 256, Q_SMEM_BYTES>>>(x);              // q -> qT + qm/qv
    ssim_kernel<<<dim3(512, 8), 256, SMEM_BYTES>>>();      // ST = exp(ssim), psum
    out_kernel<<<1024, 256, O_SMEM_BYTES>>>(out);          // out = (P @ v)/rowsum
}

// round 17
// speedup vs baseline: 2.0417x; 1.7056x over previous
#include <cuda_runtime.h>

#define NROWS 65536   // N_TOKENS * BATCH
#define FDIM  256     // HW
#define MDIM  1024    // MEM_DIM

// ---------------- scratch (static device globals; no allocation) ----------------
__device__ float g_qT[FDIM * NROWS];            // q TRANSPOSED [F, N] (tf32-rnd)  (64 MB)
__device__ float g_qm[NROWS];
__device__ float g_qv[NROWS];
__device__ float g_kcT[FDIM * MDIM];            // centered k^T [F, M] (tf32-rnd)  (1 MB)
__device__ float g_vmat[MDIM * FDIM];           // v [M, F] (tf32-rnd)             (1 MB)
__device__ float g_km[MDIM];
__device__ float g_kv[MDIM];
__device__ float g_WqT[FDIM * FDIM];            // Wq transposed [h, j]            (256 KB)
__device__ float g_ST[(size_t)MDIM * NROWS];    // p = exp(ssim) [M,N] (tf32-rnd)  (256 MB)
__device__ float g_psum[8 * NROWS];             // per-m-block partial col sums    (2 MB)

// ---------------- packed f32x2 helpers (FFMA2 path, prep kernels) ---------------
__device__ __forceinline__ unsigned long long pk2(float lo, float hi) {
    unsigned long long r;
    asm("mov.b64 %0, {%1, %2};" : "=l"(r) : "f"(lo), "f"(hi));
    return r;
}
__device__ __forceinline__ void fma2(unsigned long long& d, unsigned long long a,
                                     unsigned long long b) {
    asm("fma.rn.f32x2 %0, %1, %2, %0;" : "+l"(d) : "l"(a), "l"(b));
}
__device__ __forceinline__ float2 upk2(unsigned long long v) {
    float2 r;
    asm("mov.b64 {%0, %1}, %2;" : "=f"(r.x), "=f"(r.y) : "l"(v));
    return r;
}

// ---------------- tf32 helpers --------------------------------------------------
__device__ __forceinline__ float tf32r(float x) {   // round-to-nearest tf32 (as f32)
    unsigned u;
    asm("cvt.rna.tf32.f32 %0, %1;" : "=r"(u) : "f"(x));
    return __uint_as_float(u);
}
__device__ __forceinline__ void mma_tf32(float d[4], const unsigned a[4],
                                         const unsigned b[2]) {
    asm volatile(
        "mma.sync.aligned.m16n8k8.row.col.f32.tf32.tf32.f32 "
        "{%0,%1,%2,%3}, {%4,%5,%6,%7}, {%8,%9}, {%0,%1,%2,%3};"
        : "+f"(d[0]), "+f"(d[1]), "+f"(d[2]), "+f"(d[3])
        : "r"(a[0]), "r"(a[1]), "r"(a[2]), "r"(a[3]), "r"(b[0]), "r"(b[1]));
}

// ---------------- cp.async helpers ----------------------------------------------
__device__ __forceinline__ void cpa16(void* dst, const void* src) {
    unsigned saddr = (unsigned)__cvta_generic_to_shared(dst);
    asm volatile("cp.async.cg.shared.global [%0], [%1], 16;" ::"r"(saddr), "l"(src));
}
__device__ __forceinline__ void cpa_commit() {
    asm volatile("cp.async.commit_group;" ::: "memory");
}
__device__ __forceinline__ void cpa_wait_all() {
    asm volatile("cp.async.wait_group 0;" ::: "memory");
}

// =================================================================================
// wqt: transpose Wq [256x256] -> g_WqT.
// =================================================================================
__global__ __launch_bounds__(256) void wqt_kernel(const float* __restrict__ W) {
    __shared__ float t[32][33];
    const int bx = blockIdx.x << 5, by = blockIdx.y << 5;
    const int lx = threadIdx.x & 31, ly4 = (threadIdx.x >> 5) << 2;
#pragma unroll
    for (int i = 0; i < 4; i++)
        t[ly4 + i][lx] = W[(by + ly4 + i) * 256 + bx + lx];
    __syncthreads();
#pragma unroll
    for (int i = 0; i < 4; i++)
        g_WqT[(bx + ly4 + i) * 256 + by + lx] = t[lx][ly4 + i];
}

// =================================================================================
// rowgemm (k/v prep): C[64 x 256] = A_tile @ W^T
// MODE 1: k -> stats + centered kcT (tf32-rounded).  MODE 2: v (tf32-rounded).
// =================================================================================
template <int MODE>
__global__ __launch_bounds__(256, 2) void rowgemm_kernel(const float* __restrict__ A,
                                                         const float* __restrict__ W) {
    __shared__ float As[16][68];
    __shared__ float Bs[16][260];

    const int tid = threadIdx.x;
    const int n0  = blockIdx.x * 64;
    const int tr  = tid >> 5;
    const int tc  = tid & 31;

    unsigned long long accp[8][4];
#pragma unroll
    for (int i = 0; i < 8; i++)
#pragma unroll
        for (int j = 0; j < 4; j++) accp[i][j] = 0ull;

    for (int k0 = 0; k0 < 256; k0 += 16) {
        {
            int r = tid >> 2;
            int c = (tid & 3) << 2;
            float4 v = *(const float4*)&A[(n0 + r) * 256 + k0 + c];
            As[c + 0][r] = v.x; As[c + 1][r] = v.y; As[c + 2][r] = v.z; As[c + 3][r] = v.w;
        }
#pragma unroll
        for (int it = 0; it < 4; it++) {
            int fid = tid + (it << 8);
            int j = fid >> 2;
            int c = (fid & 3) << 2;
            float4 v = *(const float4*)&W[j * 256 + k0 + c];
            Bs[c + 0][j] = v.x; Bs[c + 1][j] = v.y; Bs[c + 2][j] = v.z; Bs[c + 3][j] = v.w;
        }
        __syncthreads();
#pragma unroll
        for (int kk = 0; kk < 16; kk++) {
            float4 a0 = *(const float4*)&As[kk][tr * 4];
            float4 a1 = *(const float4*)&As[kk][32 + tr * 4];
            ulonglong2 b0 = *(const ulonglong2*)(const void*)&Bs[kk][tc * 4];
            ulonglong2 b1 = *(const ulonglong2*)(const void*)&Bs[kk][128 + tc * 4];
            unsigned long long ap[8] = {pk2(a0.x, a0.x), pk2(a0.y, a0.y), pk2(a0.z, a0.z),
                                        pk2(a0.w, a0.w), pk2(a1.x, a1.x), pk2(a1.y, a1.y),
                                        pk2(a1.z, a1.z), pk2(a1.w, a1.w)};
            unsigned long long bv[4] = {b0.x, b0.y, b1.x, b1.y};
#pragma unroll
            for (int i = 0; i < 8; i++)
#pragma unroll
                for (int j = 0; j < 4; j++) fma2(accp[i][j], ap[i], bv[j]);
        }
        __syncthreads();
    }

    float acc[8][8];
#pragma unroll
    for (int i = 0; i < 8; i++)
#pragma unroll
        for (int j2 = 0; j2 < 4; j2++) {
            float2 u = upk2(accp[i][j2]);
            acc[i][2 * j2 + 0] = u.x;
            acc[i][2 * j2 + 1] = u.y;
        }

#pragma unroll
    for (int i = 0; i < 8; i++) {
        const int row = n0 + tr * 4 + (i & 3) + ((i >> 2) << 5);
        if (MODE == 2) {
            *(float4*)&g_vmat[row * 256 + tc * 4] =
                make_float4(tf32r(acc[i][0]), tf32r(acc[i][1]), tf32r(acc[i][2]),
                            tf32r(acc[i][3]));
            *(float4*)&g_vmat[row * 256 + 128 + tc * 4] =
                make_float4(tf32r(acc[i][4]), tf32r(acc[i][5]), tf32r(acc[i][6]),
                            tf32r(acc[i][7]));
        } else {
            float s = 0.f, ss = 0.f;
#pragma unroll
            for (int j = 0; j < 8; j++) { s += acc[i][j]; ss += acc[i][j] * acc[i][j]; }
#pragma unroll
            for (int o = 16; o > 0; o >>= 1) {
                s  += __shfl_xor_sync(0xffffffffu, s, o);
                ss += __shfl_xor_sync(0xffffffffu, ss, o);
            }
            const float mean = s * (1.0f / 256.0f);
            const float var  = (ss - 256.0f * mean * mean) * (1.0f / 255.0f);
            if (tc == 0) { g_km[row] = mean; g_kv[row] = var; }
#pragma unroll
            for (int j = 0; j < 8; j++) {
                const int col = tc * 4 + (j & 3) + ((j >> 2) << 7);
                g_kcT[col * 1024 + row] = tf32r(acc[i][j] - mean);
            }
        }
    }
}

// =================================================================================
// q_kernel: C[64n x 256j] = x_tile @ WqT (FFMA2, proven). Stats fp32 exact;
// qT store tf32-rounded (feeds ssim mma).
// =================================================================================
#define QA_STR 68
#define QB_STR 260
#define QA_BUF (32 * QA_STR)
#define QB_BUF (32 * QB_STR)
#define Q_SMEM_BYTES ((2 * QA_BUF + 2 * QB_BUF) * 4)   // 83968
#define TS_STR 65

__device__ __forceinline__ void q_lda(float4 av[2], const float* __restrict__ x,
                                      int n0, int k0, int tid) {
    const int r = tid >> 2, c = (tid & 3) << 3;
    av[0] = *(const float4*)&x[(n0 + r) * 256 + k0 + c];
    av[1] = *(const float4*)&x[(n0 + r) * 256 + k0 + c + 4];
}
__device__ __forceinline__ void q_sts(const float4 av[2], float* As, int tid) {
    const int r = tid >> 2, c = (tid & 3) << 3;
    As[(c + 0) * QA_STR + r] = av[0].x; As[(c + 1) * QA_STR + r] = av[0].y;
    As[(c + 2) * QA_STR + r] = av[0].z; As[(c + 3) * QA_STR + r] = av[0].w;
    As[(c + 4) * QA_STR + r] = av[1].x; As[(c + 5) * QA_STR + r] = av[1].y;
    As[(c + 6) * QA_STR + r] = av[1].z; As[(c + 7) * QA_STR + r] = av[1].w;
}
__device__ __forceinline__ void q_ldb(float* Bs, int k0, int tid) {
#pragma unroll
    for (int it = 0; it < 8; it++) {
        int ch = tid + (it << 8);
        int rr = ch >> 6, cc = (ch & 63) << 2;
        cpa16(&Bs[rr * QB_STR + cc], &g_WqT[(k0 + rr) * 256 + cc]);
    }
    cpa_commit();
}
template <int K0, int K1>
__device__ __forceinline__ void q_mma(const float* __restrict__ As,
                                      const float* __restrict__ Bs, int tr, int tc,
                                      unsigned long long accp[8][4]) {
#pragma unroll
    for (int kk = K0; kk < K1; kk++) {
        float4 a0 = *(const float4*)&As[kk * QA_STR + tr * 4];
        float4 a1 = *(const float4*)&As[kk * QA_STR + 32 + tr * 4];
        ulonglong2 b0 = *(const ulonglong2*)(const void*)&Bs[kk * QB_STR + tc * 4];
        ulonglong2 b1 = *(const ulonglong2*)(const void*)&Bs[kk * QB_STR + 128 + tc * 4];
        unsigned long long ap[8] = {pk2(a0.x, a0.x), pk2(a0.y, a0.y), pk2(a0.z, a0.z),
                                    pk2(a0.w, a0.w), pk2(a1.x, a1.x), pk2(a1.y, a1.y),
                                    pk2(a1.z, a1.z), pk2(a1.w, a1.w)};
        unsigned long long bv[4] = {b0.x, b0.y, b1.x, b1.y};
#pragma unroll
        for (int i = 0; i < 8; i++)
#pragma unroll
            for (int j = 0; j < 4; j++) fma2(accp[i][j], ap[i], bv[j]);
    }
}

__global__ __launch_bounds__(256, 2) void q_kernel(const float* __restrict__ x) {
    extern __shared__ float sm[];
    float* Asm[2] = {sm, sm + QA_BUF};
    float* Bsm[2] = {sm + 2 * QA_BUF, sm + 2 * QA_BUF + QB_BUF};
    float* Ts     = sm + 2 * QA_BUF;

    const int tid = threadIdx.x;
    const int n0  = blockIdx.x * 64;
    const int tr  = tid >> 5;
    const int tc  = tid & 31;

    unsigned long long accp[8][4];
#pragma unroll
    for (int i = 0; i < 8; i++)
#pragma unroll
        for (int j = 0; j < 4; j++) accp[i][j] = 0ull;

    float4 av[2];
    q_lda(av, x, n0, 0, tid);
    q_ldb(Bsm[0], 0, tid);
    q_sts(av, Asm[0], tid);
    cpa_wait_all();
    __syncthreads();

#pragma unroll 1
    for (int t = 0; t < 8; t++) {
        const bool more = (t + 1 < 8);
        if (more) {
            q_ldb(Bsm[(t + 1) & 1], (t + 1) * 32, tid);
            q_lda(av, x, n0, (t + 1) * 32, tid);
        }
        q_mma<0, 16>(Asm[t & 1], Bsm[t & 1], tr, tc, accp);
        if (more) q_sts(av, Asm[(t + 1) & 1], tid);
        q_mma<16, 32>(Asm[t & 1], Bsm[t & 1], tr, tc, accp);
        if (more) cpa_wait_all();
        __syncthreads();
    }

    float acc[8][8];
#pragma unroll
    for (int i = 0; i < 8; i++)
#pragma unroll
        for (int j2 = 0; j2 < 4; j2++) {
            float2 u = upk2(accp[i][j2]);
            acc[i][2 * j2 + 0] = u.x;
            acc[i][2 * j2 + 1] = u.y;
        }

#pragma unroll
    for (int i = 0; i < 8; i++) {
        const int rloc = tr * 4 + (i & 3) + ((i >> 2) << 5);
        const int row  = n0 + rloc;
        float s = 0.f, ss = 0.f;
#pragma unroll
        for (int j = 0; j < 8; j++) { s += acc[i][j]; ss += acc[i][j] * acc[i][j]; }
#pragma unroll
        for (int o = 16; o > 0; o >>= 1) {
            s  += __shfl_xor_sync(0xffffffffu, s, o);
            ss += __shfl_xor_sync(0xffffffffu, ss, o);
        }
        const float mean = s * (1.0f / 256.0f);
        const float var  = (ss - 256.0f * mean * mean) * (1.0f / 255.0f);
        if (tc == 0) { g_qm[row] = mean; g_qv[row] = var; }
#pragma unroll
        for (int j = 0; j < 8; j++) {
            const int f = tc * 4 + (j & 3) + ((j >> 2) << 7);
            Ts[f * TS_STR + rloc] = tf32r(acc[i][j]);   // raw q, tf32-rounded
        }
    }

    __syncthreads();
    const float* src = &Ts[tid * TS_STR];
    float* dst = &g_qT[(size_t)tid * NROWS + n0];
#pragma unroll
    for (int r = 0; r < 64; r += 4)
        *(float4*)&dst[r] = make_float4(src[r], src[r + 1], src[r + 2], src[r + 3]);
}

// =================================================================================
// ssim (tf32 mma): 128m x 128n block, K=256 in 8 chunks of 32, cp.async buffered.
// Warp (of 8): wm = w&1 (64m), wn = w>>2... wn = w>>1 (32n). Warp tile 64m x 32n =
// 4x4 m16n8k8 mma. A = kcT chunk [32k][128m], B = qT chunk [32k][128n], K-major.
// Epilogue: SSIM map + exp (stats fp32), tf32-rounded store + deterministic psum.
// =================================================================================
#define T_STR 132
#define T_BUF (32 * T_STR)
#define SMEM_BYTES (4 * T_BUF * 4)    // 67584 bytes

__device__ __forceinline__ void ld_tile(float* dst, const float* __restrict__ src,
                                        size_t row_stride, int tid) {
#pragma unroll
    for (int it = 0; it < 4; it++) {
        int ch = tid + (it << 8);
        int rr = ch >> 5, cc = (ch & 31) << 2;
        cpa16(&dst[rr * T_STR + cc], &src[(size_t)rr * row_stride + cc]);
    }
}

__global__ __launch_bounds__(256, 2) void ssim_kernel() {
    extern __shared__ float sm[];
    float* Asm[2] = {sm, sm + T_BUF};
    float* Bsm[2] = {sm + 2 * T_BUF, sm + 3 * T_BUF};

    const int tid  = threadIdx.x;
    const int n0   = blockIdx.x << 7;
    const int m0   = blockIdx.y << 7;
    const int lane = tid & 31;
    const int w    = tid >> 5;
    const int wm   = w & 1;        // m-half (64)
    const int wn   = w >> 1;       // n-quarter (32)
    const int g    = lane >> 2;
    const int t    = lane & 3;

    float d[4][4][4];
#pragma unroll
    for (int mi = 0; mi < 4; mi++)
#pragma unroll
        for (int ni = 0; ni < 4; ni++)
#pragma unroll
            for (int r = 0; r < 4; r++) d[mi][ni][r] = 0.f;

    ld_tile(Asm[0], &g_kcT[m0], 1024, tid);
    ld_tile(Bsm[0], &g_qT[n0], NROWS, tid);
    cpa_commit();
    cpa_wait_all();
    __syncthreads();

#pragma unroll 1
    for (int tt = 0; tt < 8; tt++) {
        const bool more = (tt + 1 < 8);
        if (more) {
            ld_tile(Asm[(tt + 1) & 1], &g_kcT[(tt + 1) * 32 * 1024 + m0], 1024, tid);
            ld_tile(Bsm[(tt + 1) & 1], &g_qT[(size_t)(tt + 1) * 32 * NROWS + n0], NROWS,
                    tid);
            cpa_commit();
        }
        const float* As = Asm[tt & 1];
        const float* Bs = Bsm[tt & 1];
#pragma unroll
        for (int kt = 0; kt < 4; kt++) {
            const float* a0p = As + (kt * 8 + t) * T_STR;
            const float* a4p = a0p + 4 * T_STR;
            const float* b0p = Bs + (kt * 8 + t) * T_STR;
            const float* b4p = b0p + 4 * T_STR;
            unsigned av[4][4], bv[4][2];
#pragma unroll
            for (int mi = 0; mi < 4; mi++) {
                const int mb = wm * 64 + mi * 16 + g;
                av[mi][0] = __float_as_uint(a0p[mb]);
                av[mi][1] = __float_as_uint(a0p[mb + 8]);
                av[mi][2] = __float_as_uint(a4p[mb]);
                av[mi][3] = __float_as_uint(a4p[mb + 8]);
            }
#pragma unroll
            for (int ni = 0; ni < 4; ni++) {
                const int nb = wn * 32 + ni * 8 + g;
                bv[ni][0] = __float_as_uint(b0p[nb]);
                bv[ni][1] = __float_as_uint(b4p[nb]);
            }
#pragma unroll
            for (int mi = 0; mi < 4; mi++)
#pragma unroll
                for (int ni = 0; ni < 4; ni++) mma_tf32(d[mi][ni], av[mi], bv[ni]);
        }
        if (more) cpa_wait_all();
        __syncthreads();
    }

    // ---- SSIM epilogue ----
    const float C1f = 0.01f, C2f = 0.03f, EPSf = 1e-8f, INV255 = 1.0f / 255.0f;

    float km_[4][2], kv_[4][2];
#pragma unroll
    for (int mi = 0; mi < 4; mi++)
#pragma unroll
        for (int h = 0; h < 2; h++) {
            const int mrow = m0 + wm * 64 + mi * 16 + g + h * 8;
            km_[mi][h] = g_km[mrow];
            kv_[mi][h] = g_kv[mrow];
        }
    float qm_[4][2], qv_[4][2];
#pragma unroll
    for (int ni = 0; ni < 4; ni++)
#pragma unroll
        for (int c = 0; c < 2; c++) {
            const int ncol = n0 + wn * 32 + ni * 8 + 2 * t + c;
            qm_[ni][c] = g_qm[ncol];
            qv_[ni][c] = g_qv[ncol];
        }

    float cp[4][2];
#pragma unroll
    for (int ni = 0; ni < 4; ni++) { cp[ni][0] = 0.f; cp[ni][1] = 0.f; }

#pragma unroll
    for (int mi = 0; mi < 4; mi++)
#pragma unroll
        for (int h = 0; h < 2; h++) {
            const int mrow = m0 + wm * 64 + mi * 16 + g + h * 8;
#pragma unroll
            for (int ni = 0; ni < 4; ni++) {
                float p[2];
#pragma unroll
                for (int c = 0; c < 2; c++) {
                    const float cov = d[mi][ni][2 * h + c] * INV255;
                    const float num =
                        (2.0f * qm_[ni][c] * km_[mi][h] + C1f) * (2.0f * cov + C2f);
                    const float den = (qm_[ni][c] * qm_[ni][c] + km_[mi][h] * km_[mi][h] +
                                       C1f) * (qv_[ni][c] + kv_[mi][h] + C2f) + EPSf;
                    p[c] = tf32r(__expf(__fdividef(num, den)));
                    cp[ni][c] += p[c];
                }
                *(float2*)&g_ST[(size_t)mrow * NROWS + n0 + wn * 32 + ni * 8 + 2 * t] =
                    make_float2(p[0], p[1]);
            }
        }

    // reduce cp over g (lanes xor 4,8,16) -> per-warp col sums over its 64 m
#pragma unroll
    for (int ni = 0; ni < 4; ni++)
#pragma unroll
        for (int c = 0; c < 2; c++) {
#pragma unroll
            for (int o = 4; o <= 16; o <<= 1)
                cp[ni][c] += __shfl_xor_sync(0xffffffffu, cp[ni][c], o);
        }
    float* red = sm;   // 256 floats: [wm][128 n]
    if (g == 0) {
#pragma unroll
        for (int ni = 0; ni < 4; ni++)
#pragma unroll
            for (int c = 0; c < 2; c++)
                red[wm * 128 + wn * 32 + ni * 8 + 2 * t + c] = cp[ni][c];
    }
    __syncthreads();
    if (tid < 128)
        g_psum[blockIdx.y * NROWS + n0 + tid] = red[tid] + red[128 + tid];
}

// =================================================================================
// out (tf32 mma): out[64n x 256f] = (P @ v) / rowsum.  K = 1024 m, 32 chunks.
// Warp: wn2 = w&1 (32n), wf = w>>1 (64f). Warp tile 32n x 64f = 2x8 mma.
// A = ST chunk [32m][64n], B = v chunk [32m][256f], both K-major verbatim.
// =================================================================================
#define OA_STR 68
#define OB_STR 260
#define OA_BUF (32 * OA_STR)
#define OB_BUF (32 * OB_STR)
#define O_SMEM_BYTES ((2 * OA_BUF + 2 * OB_BUF) * 4)   // 83968

__device__ __forceinline__ void o_lda(float* dst, int t, int n0, int tid) {
#pragma unroll
    for (int it = 0; it < 2; it++) {
        int ch = tid + (it << 8);
        int rr = ch >> 4, cc = (ch & 15) << 2;
        cpa16(&dst[rr * OA_STR + cc], &g_ST[(size_t)(t * 32 + rr) * NROWS + n0 + cc]);
    }
}
__device__ __forceinline__ void o_ldb(float* dst, int t, int tid) {
#pragma unroll
    for (int it = 0; it < 8; it++) {
        int ch = tid + (it << 8);
        int rr = ch >> 6, cc = (ch & 63) << 2;
        cpa16(&dst[rr * OB_STR + cc], &g_vmat[(t * 32 + rr) * 256 + cc]);
    }
}

__global__ __launch_bounds__(256, 2) void out_kernel(float* __restrict__ out) {
    extern __shared__ float sm[];
    float* Asm[2] = {sm, sm + OA_BUF};
    float* Bsm[2] = {sm + 2 * OA_BUF, sm + 2 * OA_BUF + OB_BUF};

    const int tid  = threadIdx.x;
    const int n0   = blockIdx.x << 6;
    const int lane = tid & 31;
    const int w    = tid >> 5;
    const int wn2  = w & 1;        // n-half (32)
    const int wf   = w >> 1;       // f-quarter (64)
    const int g    = lane >> 2;
    const int t    = lane & 3;

    float d[2][8][4];
#pragma unroll
    for (int mi = 0; mi < 2; mi++)
#pragma unroll
        for (int ni = 0; ni < 8; ni++)
#pragma unroll
            for (int r = 0; r < 4; r++) d[mi][ni][r] = 0.f;

    o_lda(Asm[0], 0, n0, tid);
    o_ldb(Bsm[0], 0, tid);
    cpa_commit();
    cpa_wait_all();
    __syncthreads();

#pragma unroll 1
    for (int tt = 0; tt < 32; tt++) {
        const bool more = (tt + 1 < 32);
        if (more) {
            o_lda(Asm[(tt + 1) & 1], tt + 1, n0, tid);
            o_ldb(Bsm[(tt + 1) & 1], tt + 1, tid);
            cpa_commit();
        }
        const float* As = Asm[tt & 1];
        const float* Bs = Bsm[tt & 1];
#pragma unroll
        for (int kt = 0; kt < 4; kt++) {
            const float* a0p = As + (kt * 8 + t) * OA_STR;
            const float* a4p = a0p + 4 * OA_STR;
            const float* b0p = Bs + (kt * 8 + t) * OB_STR;
            const float* b4p = b0p + 4 * OB_STR;
            unsigned av[2][4], bv[8][2];
#pragma unroll
            for (int mi = 0; mi < 2; mi++) {
                const int nb = wn2 * 32 + mi * 16 + g;
                av[mi][0] = __float_as_uint(a0p[nb]);
                av[mi][1] = __float_as_uint(a0p[nb + 8]);
                av[mi][2] = __float_as_uint(a4p[nb]);
                av[mi][3] = __float_as_uint(a4p[nb + 8]);
            }
#pragma unroll
            for (int ni = 0; ni < 8; ni++) {
                const int fb = wf * 64 + ni * 8 + g;
                bv[ni][0] = __float_as_uint(b0p[fb]);
                bv[ni][1] = __float_as_uint(b4p[fb]);
            }
#pragma unroll
            for (int mi = 0; mi < 2; mi++)
#pragma unroll
                for (int ni = 0; ni < 8; ni++) mma_tf32(d[mi][ni], av[mi], bv[ni]);
        }
        if (more) cpa_wait_all();
        __syncthreads();
    }

    // ---- normalize + store ----
    float inv[2][2];
#pragma unroll
    for (int mi = 0; mi < 2; mi++)
#pragma unroll
        for (int h = 0; h < 2; h++) {
            const int nrow = n0 + wn2 * 32 + mi * 16 + g + h * 8;
            float s = 0.f;
#pragma unroll
            for (int b = 0; b < 8; b++) s += g_psum[b * NROWS + nrow];
            inv[mi][h] = 1.0f / s;
        }
#pragma unroll
    for (int mi = 0; mi < 2; mi++)
#pragma unroll
        for (int h = 0; h < 2; h++) {
            const int nrow = n0 + wn2 * 32 + mi * 16 + g + h * 8;
#pragma unroll
            for (int ni = 0; ni < 8; ni++) {
                const int f0 = wf * 64 + ni * 8 + 2 * t;
                *(float2*)&out[nrow * 256 + f0] =
                    make_float2(d[mi][ni][2 * h + 0] * inv[mi][h],
                                d[mi][ni][2 * h + 1] * inv[mi][h]);
            }
        }
}

// =================================================================================
extern "C" void kernel_launch(void* const* d_in, const int* in_sizes, int n_in,
                              void* d_out, int out_size) {
    (void)in_sizes; (void)n_in; (void)out_size;
    const float* x   = (const float*)d_in[0];   // [8192, 8, 256] -> [65536, 256]
    const float* mem = (const float*)d_in[1];   // [1024, 16, 16] -> [1024, 256]
    const float* Wq  = (const float*)d_in[2];   // [256, 256]
    const float* Wk  = (const float*)d_in[3];
    const float* Wv  = (const float*)d_in[4];
    float* out = (float*)d_out;

    cudaFuncSetAttribute(q_kernel, cudaFuncAttributeMaxDynamicSharedMemorySize,
                         Q_SMEM_BYTES);
    cudaFuncSetAttribute(ssim_kernel, cudaFuncAttributeMaxDynamicSharedMemorySize,
                         SMEM_BYTES);
    cudaFuncSetAttribute(out_kernel, cudaFuncAttributeMaxDynamicSharedMemorySize,
                         O_SMEM_BYTES);

    wqt_kernel<<<dim3(8, 8), 256>>>(Wq);                   // WqT
    rowgemm_kernel<1><<<16, 256>>>(mem, Wk);               // kcT (tf32) + km/kv
    rowgemm_kernel<2><<<16, 256>>>(mem, Wv);               // v (tf32)
    q_kernel<<<1024, 256, Q_SMEM_BYTES>>>(x);              // qT (tf32) + qm/qv
    ssim_kernel<<<dim3(512, 8), 256, SMEM_BYTES>>>();      // ST = exp(ssim), psum
    out_kernel<<<1024, 256, O_SMEM_BYTES>>>(out);          // out = (P @ v)/rowsum
}